// round 14
// baseline (speedup 1.0000x reference)
#include <cuda_runtime.h>
#include <cuda_bf16.h>
#include <cuda_fp16.h>
#include <cstdint>

#define N_NODES 100000
#define D 128

// ---------------- scratch (device globals: no allocations allowed) ----------
__device__ int    g_rowptr[N_NODES + 1];
__device__ __half g_hW[(size_t)N_NODES * D];   // h @ W.T in fp16, 25.6 MB
// Pre-swizzled W fragments for mma.sync m16n8k16 fp16.
__device__ uint2 g_Whf[8 * 16 * 32];

// ---------------- Kernel 1: row_ptr via scatter over sorted rows ------------
__global__ void rowptr_kernel(const int* __restrict__ rows, int n_edges) {
    int e = blockIdx.x * blockDim.x + threadIdx.x;
    if (e >= n_edges) return;
    int b = __ldg(&rows[e]);
    if (e == 0) {
        for (int i = 0; i <= b; i++) g_rowptr[i] = 0;
    } else {
        int a = __ldg(&rows[e - 1]);
        for (int i = a + 1; i <= b; i++) g_rowptr[i] = e;
    }
    if (e == n_edges - 1) {
        for (int i = b + 1; i <= N_NODES; i++) g_rowptr[i] = n_edges;
    }
}

// ---------------- Kernel 1b: W fragment prep (fp16) -------------------------
__device__ __forceinline__ uint32_t pack2_h16(float x, float y) {
    __half2 v = __floats2half2_rn(x, y);
    return *(uint32_t*)&v;
}

__global__ void wprep_kernel(const float* __restrict__ W) {
    int t = blockIdx.x * blockDim.x + threadIdx.x;   // 0..4095
    if (t >= 8 * 16 * 32) return;
    int lane  = t & 31;
    int ntile = (t >> 5) & 15;
    int kstep = t >> 9;

    int n  = ntile * 8 + (lane >> 2);
    int k0 = kstep * 16 + (lane & 3) * 2;

    float w00 = __ldg(&W[n * 128 + k0]);
    float w01 = __ldg(&W[n * 128 + k0 + 1]);
    float w10 = __ldg(&W[n * 128 + k0 + 8]);
    float w11 = __ldg(&W[n * 128 + k0 + 9]);

    uint2 f;
    f.x = pack2_h16(w00, w01);
    f.y = pack2_h16(w10, w11);
    g_Whf[t] = f;
}

// ---------------- Kernel 2: g = h @ W.T, smem-staged fp16 mma ----------------
// (unchanged — measured improvement)
#define MTILE 64
#define APAD  136

__device__ __forceinline__ void mma_f16(float* c, const uint32_t* a, uint2 b) {
    asm volatile(
        "mma.sync.aligned.m16n8k16.row.col.f32.f16.f16.f32 "
        "{%0,%1,%2,%3}, {%4,%5,%6,%7}, {%8,%9}, {%0,%1,%2,%3};"
        : "+f"(c[0]), "+f"(c[1]), "+f"(c[2]), "+f"(c[3])
        : "r"(a[0]), "r"(a[1]), "r"(a[2]), "r"(a[3]), "r"(b.x), "r"(b.y));
}

__global__ void __launch_bounds__(128, 4) gemm_kernel(
    const float* __restrict__ A)   // h [N_NODES, 128]
{
    __shared__ __half sA[MTILE * APAD];   // 17.4 KB

    const int tid    = threadIdx.x;
    const int lane   = tid & 31;
    const int warp   = tid >> 5;
    const int m_base = blockIdx.x * MTILE;

    #pragma unroll
    for (int q = 0; q < 16; q++) {
        int idx = q * 128 + tid;          // 0..2047
        int row = idx >> 5;
        int c4  = idx & 31;
        int rsrc = min(m_base + row, N_NODES - 1);
        float4 v = __ldg(&((const float4*)A)[(size_t)rsrc * 32 + c4]);
        __half2 p0 = __floats2half2_rn(v.x, v.y);
        __half2 p1 = __floats2half2_rn(v.z, v.w);
        *(__half2*)&sA[row * APAD + c4 * 4]     = p0;
        *(__half2*)&sA[row * APAD + c4 * 4 + 2] = p1;
    }
    __syncthreads();

    const int grp  = lane >> 2;
    const int quad = lane & 3;
    const int mrow = (warp >> 1) * 32;
    const int ntb  = (warp & 1) * 8;

    float acc[2][8][4];
    #pragma unroll
    for (int f = 0; f < 2; f++)
        #pragma unroll
        for (int nt = 0; nt < 8; nt++)
            #pragma unroll
            for (int i = 0; i < 4; i++) acc[f][nt][i] = 0.f;

    #pragma unroll
    for (int kstep = 0; kstep < 8; kstep++) {
        int kb = kstep * 16 + quad * 2;
        uint32_t a[2][4];
        #pragma unroll
        for (int f = 0; f < 2; f++) {
            int r = mrow + f * 16 + grp;
            a[f][0] = *(uint32_t*)&sA[r * APAD + kb];
            a[f][1] = *(uint32_t*)&sA[(r + 8) * APAD + kb];
            a[f][2] = *(uint32_t*)&sA[r * APAD + kb + 8];
            a[f][3] = *(uint32_t*)&sA[(r + 8) * APAD + kb + 8];
        }
        #pragma unroll
        for (int nt = 0; nt < 8; nt++) {
            uint2 wh = __ldg(&g_Whf[(kstep * 16 + ntb + nt) * 32 + lane]);
            mma_f16(acc[0][nt], a[0], wh);
            mma_f16(acc[1][nt], a[1], wh);
        }
    }
    __syncthreads();

    #pragma unroll
    for (int f = 0; f < 2; f++) {
        #pragma unroll
        for (int nt = 0; nt < 8; nt++) {
            int col = (ntb + nt) * 8 + quad * 2;
            int r0  = mrow + f * 16 + grp;
            *(__half2*)&sA[r0 * APAD + col] =
                __floats2half2_rn(acc[f][nt][0], acc[f][nt][1]);
            *(__half2*)&sA[(r0 + 8) * APAD + col] =
                __floats2half2_rn(acc[f][nt][2], acc[f][nt][3]);
        }
    }
    __syncthreads();

    #pragma unroll
    for (int q = 0; q < 8; q++) {
        int idx = q * 128 + tid;          // 0..1023
        int row = idx >> 4;
        int c16 = idx & 15;
        int rdst = m_base + row;
        if (rdst < N_NODES) {
            uint4 v = *(uint4*)&sA[row * APAD + c16 * 8];
            *(uint4*)&g_hW[(size_t)rdst * 128 + c16 * 8] = v;
        }
    }
}

// ---------------- Kernel 3: SpMM, warp per node, 1-line LDG.32 gathers ------
// Lane l owns feature pairs (2l, 2l+1) and (64+2l, 64+2l+1). Per edge the
// warp issues two LDG.32s, each touching EXACTLY one 128B line of the row
// (cross-LDG 1.0 cyc/wf instead of within-LDG 2.07 replays). Edge chunks of
// 32; inner processing in warp-uniform groups of 8 (16 loads in flight).
__global__ void __launch_bounds__(256) spmm_kernel(
    const int*   __restrict__ cols,
    const float* __restrict__ vals,
    const float* __restrict__ bias,
    float*       __restrict__ out)
{
    const int nid = (blockIdx.x * blockDim.x + threadIdx.x) >> 5;
    const unsigned lane = threadIdx.x & 31;
    if (nid >= N_NODES) return;

    const int start = g_rowptr[nid];
    const int end   = g_rowptr[nid + 1];

    const __half2* __restrict__ g2 = ((const __half2*)g_hW) + lane;  // row = 64 h2

    float acc0 = 0.f, acc1 = 0.f, acc2 = 0.f, acc3 = 0.f;

    for (int base = start; base < end; base += 32) {
        const int avail = min(32, end - base);       // warp-uniform
        int   c = 0; float v = 0.f;
        if ((int)lane < avail) {
            c = __ldg(&cols[base + lane]);
            v = __ldg(&vals[base + lane]);
        }
        const int ng = (avail + 7) >> 3;             // warp-uniform, 1..4
        for (int g = 0; g < ng; g++) {
            #pragma unroll
            for (int j = 0; j < 8; j++) {
                unsigned cj = (unsigned)__shfl_sync(0xffffffffu, c, g * 8 + j);
                float    vj = __shfl_sync(0xffffffffu, v, g * 8 + j);
                __half2 lo = __ldg(&g2[cj * 64u]);        // line 0 of row
                __half2 hi = __ldg(&g2[cj * 64u + 32u]);  // line 1 of row
                float2 flo = __half22float2(lo);
                float2 fhi = __half22float2(hi);
                acc0 = fmaf(vj, flo.x, acc0);
                acc1 = fmaf(vj, flo.y, acc1);
                acc2 = fmaf(vj, fhi.x, acc2);
                acc3 = fmaf(vj, fhi.y, acc3);
            }
        }
    }

    const float2* b2 = (const float2*)bias;
    float2 ba = __ldg(&b2[lane]);          // b[2l], b[2l+1]
    float2 bb = __ldg(&b2[lane + 32]);     // b[64+2l], b[64+2l+1]
    float2 o0, o1;
    o0.x = fmaxf(acc0 + ba.x, 0.f);
    o0.y = fmaxf(acc1 + ba.y, 0.f);
    o1.x = fmaxf(acc2 + bb.x, 0.f);
    o1.y = fmaxf(acc3 + bb.y, 0.f);
    float2* orow = ((float2*)out) + (size_t)nid * 64;
    orow[lane]      = o0;                  // features 2l, 2l+1
    orow[lane + 32] = o1;                  // features 64+2l, 64+2l+1
}

// ---------------- launch ----------------------------------------------------
extern "C" void kernel_launch(void* const* d_in, const int* in_sizes, int n_in,
                              void* d_out, int out_size)
{
    const int*   edge_rows = (const int*)  d_in[0];
    const int*   edge_cols = (const int*)  d_in[1];
    const float* edge_vals = (const float*)d_in[2];
    const float* h         = (const float*)d_in[3];
    const float* W         = (const float*)d_in[4];
    const float* b         = (const float*)d_in[5];
    float*       out       = (float*)d_out;

    const int n_edges = in_sizes[0];

    // 1) row_ptr (scatter) + W fragment prep
    {
        int threads = 256;
        int blocks  = (n_edges + threads - 1) / threads;
        rowptr_kernel<<<blocks, threads>>>(edge_rows, n_edges);
        wprep_kernel<<<16, 256>>>(W);
    }

    // 2) g = h @ W.T  (smem-staged fp16 tensor cores, fp32 accumulate)
    {
        int blocks = (N_NODES + MTILE - 1) / MTILE;   // 1563
        gemm_kernel<<<blocks, 128>>>(h);
    }

    // 3) SpMM + bias + relu  (warp per node)
    {
        int warps_per_block = 8;             // 256 threads
        int blocks = (N_NODES + warps_per_block - 1) / warps_per_block;  // 12500
        spmm_kernel<<<blocks, 256>>>(edge_cols, edge_vals, b, out);
    }
}

// round 15
// speedup vs baseline: 1.1266x; 1.1266x over previous
#include <cuda_runtime.h>
#include <cuda_bf16.h>
#include <cuda_fp16.h>
#include <cstdint>

#define N_NODES 100000
#define D 128

// ---------------- scratch (device globals: no allocations allowed) ----------
__device__ int    g_rowptr[N_NODES + 1];
__device__ __half g_hW[(size_t)N_NODES * D];   // h @ W.T in fp16, 25.6 MB
// Pre-swizzled W fragments for mma.sync m16n8k16 fp16.
__device__ uint2 g_Whf[8 * 16 * 32];

// ---------------- Kernel 1: merged row_ptr scatter + W fragment prep --------
__device__ __forceinline__ uint32_t pack2_h16(float x, float y) {
    __half2 v = __floats2half2_rn(x, y);
    return *(uint32_t*)&v;
}

__global__ void prep_kernel(const int* __restrict__ rows, int n_edges,
                            const float* __restrict__ W) {
    int e = blockIdx.x * blockDim.x + threadIdx.x;

    // W fragment prep on the first 4096 threads.
    if (e < 8 * 16 * 32) {
        int t = e;
        int lane  = t & 31;
        int ntile = (t >> 5) & 15;
        int kstep = t >> 9;
        int n  = ntile * 8 + (lane >> 2);
        int k0 = kstep * 16 + (lane & 3) * 2;
        float w00 = __ldg(&W[n * 128 + k0]);
        float w01 = __ldg(&W[n * 128 + k0 + 1]);
        float w10 = __ldg(&W[n * 128 + k0 + 8]);
        float w11 = __ldg(&W[n * 128 + k0 + 9]);
        uint2 f;
        f.x = pack2_h16(w00, w01);
        f.y = pack2_h16(w10, w11);
        g_Whf[t] = f;
    }

    // row_ptr scatter.
    if (e >= n_edges) return;
    int b = __ldg(&rows[e]);
    if (e == 0) {
        for (int i = 0; i <= b; i++) g_rowptr[i] = 0;
    } else {
        int a = __ldg(&rows[e - 1]);
        for (int i = a + 1; i <= b; i++) g_rowptr[i] = e;
    }
    if (e == n_edges - 1) {
        for (int i = b + 1; i <= N_NODES; i++) g_rowptr[i] = n_edges;
    }
}

// ---------------- Kernel 2: g = h @ W.T, smem-staged fp16 mma ----------------
// (unchanged — measured improvement)
#define MTILE 64
#define APAD  136

__device__ __forceinline__ void mma_f16(float* c, const uint32_t* a, uint2 b) {
    asm volatile(
        "mma.sync.aligned.m16n8k16.row.col.f32.f16.f16.f32 "
        "{%0,%1,%2,%3}, {%4,%5,%6,%7}, {%8,%9}, {%0,%1,%2,%3};"
        : "+f"(c[0]), "+f"(c[1]), "+f"(c[2]), "+f"(c[3])
        : "r"(a[0]), "r"(a[1]), "r"(a[2]), "r"(a[3]), "r"(b.x), "r"(b.y));
}

__global__ void __launch_bounds__(128, 4) gemm_kernel(
    const float* __restrict__ A)   // h [N_NODES, 128]
{
    __shared__ __half sA[MTILE * APAD];   // 17.4 KB

    const int tid    = threadIdx.x;
    const int lane   = tid & 31;
    const int warp   = tid >> 5;
    const int m_base = blockIdx.x * MTILE;

    #pragma unroll
    for (int q = 0; q < 16; q++) {
        int idx = q * 128 + tid;          // 0..2047
        int row = idx >> 5;
        int c4  = idx & 31;
        int rsrc = min(m_base + row, N_NODES - 1);
        float4 v = __ldg(&((const float4*)A)[(size_t)rsrc * 32 + c4]);
        __half2 p0 = __floats2half2_rn(v.x, v.y);
        __half2 p1 = __floats2half2_rn(v.z, v.w);
        *(__half2*)&sA[row * APAD + c4 * 4]     = p0;
        *(__half2*)&sA[row * APAD + c4 * 4 + 2] = p1;
    }
    __syncthreads();

    const int grp  = lane >> 2;
    const int quad = lane & 3;
    const int mrow = (warp >> 1) * 32;
    const int ntb  = (warp & 1) * 8;

    float acc[2][8][4];
    #pragma unroll
    for (int f = 0; f < 2; f++)
        #pragma unroll
        for (int nt = 0; nt < 8; nt++)
            #pragma unroll
            for (int i = 0; i < 4; i++) acc[f][nt][i] = 0.f;

    #pragma unroll
    for (int kstep = 0; kstep < 8; kstep++) {
        int kb = kstep * 16 + quad * 2;
        uint32_t a[2][4];
        #pragma unroll
        for (int f = 0; f < 2; f++) {
            int r = mrow + f * 16 + grp;
            a[f][0] = *(uint32_t*)&sA[r * APAD + kb];
            a[f][1] = *(uint32_t*)&sA[(r + 8) * APAD + kb];
            a[f][2] = *(uint32_t*)&sA[r * APAD + kb + 8];
            a[f][3] = *(uint32_t*)&sA[(r + 8) * APAD + kb + 8];
        }
        #pragma unroll
        for (int nt = 0; nt < 8; nt++) {
            uint2 wh = __ldg(&g_Whf[(kstep * 16 + ntb + nt) * 32 + lane]);
            mma_f16(acc[0][nt], a[0], wh);
            mma_f16(acc[1][nt], a[1], wh);
        }
    }
    __syncthreads();

    #pragma unroll
    for (int f = 0; f < 2; f++) {
        #pragma unroll
        for (int nt = 0; nt < 8; nt++) {
            int col = (ntb + nt) * 8 + quad * 2;
            int r0  = mrow + f * 16 + grp;
            *(__half2*)&sA[r0 * APAD + col] =
                __floats2half2_rn(acc[f][nt][0], acc[f][nt][1]);
            *(__half2*)&sA[(r0 + 8) * APAD + col] =
                __floats2half2_rn(acc[f][nt][2], acc[f][nt][3]);
        }
    }
    __syncthreads();

    #pragma unroll
    for (int q = 0; q < 8; q++) {
        int idx = q * 128 + tid;          // 0..1023
        int row = idx >> 4;
        int c16 = idx & 15;
        int rdst = m_base + row;
        if (rdst < N_NODES) {
            uint4 v = *(uint4*)&sA[row * APAD + c16 * 8];
            *(uint4*)&g_hW[(size_t)rdst * 128 + c16 * 8] = v;
        }
    }
}

// ---------------- Kernel 3: SpMM, half-warp per node, hfma2 flush-8 ---------
// R11 skeleton (half-warp per node, static 16-edge trips, warp-uniform trip
// count) with fp16x2 inner accumulation flushed to fp32 every 8 edges.
// Padded lanes carry v=0 -> hfma2 exact no-op.
__global__ void __launch_bounds__(256) spmm_kernel(
    const int*   __restrict__ cols,
    const float* __restrict__ vals,
    const float* __restrict__ bias,
    float*       __restrict__ out)
{
    const int warp_id = (blockIdx.x * blockDim.x + threadIdx.x) >> 5;
    const unsigned lane = threadIdx.x & 31;
    const unsigned hl   = lane & 15;          // lane within half-warp
    const int nid = warp_id * 2 + (int)(lane >> 4);
    if (warp_id * 2 >= N_NODES) return;

    int start = 0, end = 0;
    if (nid < N_NODES) {
        start = g_rowptr[nid];
        end   = g_rowptr[nid + 1];
    }
    const int deg  = end - start;
    const int odeg = __shfl_xor_sync(0xffffffffu, deg, 16);
    const int ntrips = (max(deg, odeg) + 15) >> 4;   // warp-uniform

    const uint4* __restrict__ g4 = ((const uint4*)g_hW) + hl;   // row = 16 uint4

    float acc[8];
    #pragma unroll
    for (int i = 0; i < 8; i++) acc[i] = 0.f;

    for (int t = 0; t < ntrips; t++) {
        int e = start + t * 16 + (int)hl;
        int   c = 0; float v = 0.f;
        if (e < end) {
            c = __ldg(&cols[e]);
            v = __ldg(&vals[e]);
        }
        #pragma unroll
        for (int half = 0; half < 2; half++) {
            __half2 h0 = __float2half2_rn(0.f);
            __half2 h1 = __float2half2_rn(0.f);
            __half2 h2 = __float2half2_rn(0.f);
            __half2 h3 = __float2half2_rn(0.f);
            #pragma unroll
            for (int j = 0; j < 8; j++) {
                const int jj = half * 8 + j;
                unsigned cj = (unsigned)__shfl_sync(0xffffffffu, c, jj, 16);
                float    vj = __shfl_sync(0xffffffffu, v, jj, 16);
                __half2  vh = __float2half2_rn(vj);
                uint4 raw = __ldg(&g4[cj * 16u]);
                h0 = __hfma2(vh, *(__half2*)&raw.x, h0);
                h1 = __hfma2(vh, *(__half2*)&raw.y, h1);
                h2 = __hfma2(vh, *(__half2*)&raw.z, h2);
                h3 = __hfma2(vh, *(__half2*)&raw.w, h3);
            }
            // Flush to fp32.
            float2 f0 = __half22float2(h0);
            float2 f1 = __half22float2(h1);
            float2 f2 = __half22float2(h2);
            float2 f3 = __half22float2(h3);
            acc[0] += f0.x;  acc[1] += f0.y;
            acc[2] += f1.x;  acc[3] += f1.y;
            acc[4] += f2.x;  acc[5] += f2.y;
            acc[6] += f3.x;  acc[7] += f3.y;
        }
    }

    if (nid < N_NODES) {
        const float4* b4 = ((const float4*)bias) + hl * 2;
        float4 ba = __ldg(&b4[0]);
        float4 bb = __ldg(&b4[1]);
        float4 o0, o1;
        o0.x = fmaxf(acc[0] + ba.x, 0.f);
        o0.y = fmaxf(acc[1] + ba.y, 0.f);
        o0.z = fmaxf(acc[2] + ba.z, 0.f);
        o0.w = fmaxf(acc[3] + ba.w, 0.f);
        o1.x = fmaxf(acc[4] + bb.x, 0.f);
        o1.y = fmaxf(acc[5] + bb.y, 0.f);
        o1.z = fmaxf(acc[6] + bb.z, 0.f);
        o1.w = fmaxf(acc[7] + bb.w, 0.f);
        float4* orow = ((float4*)out) + (size_t)nid * 32 + hl * 2;
        orow[0] = o0;
        orow[1] = o1;
    }
}

// ---------------- launch ----------------------------------------------------
extern "C" void kernel_launch(void* const* d_in, const int* in_sizes, int n_in,
                              void* d_out, int out_size)
{
    const int*   edge_rows = (const int*)  d_in[0];
    const int*   edge_cols = (const int*)  d_in[1];
    const float* edge_vals = (const float*)d_in[2];
    const float* h         = (const float*)d_in[3];
    const float* W         = (const float*)d_in[4];
    const float* b         = (const float*)d_in[5];
    float*       out       = (float*)d_out;

    const int n_edges = in_sizes[0];

    // 1) merged row_ptr scatter + W fragment prep
    {
        int threads = 256;
        int blocks  = (n_edges + threads - 1) / threads;
        prep_kernel<<<blocks, threads>>>(edge_rows, n_edges, W);
    }

    // 2) g = h @ W.T  (smem-staged fp16 tensor cores, fp32 accumulate)
    {
        int blocks = (N_NODES + MTILE - 1) / MTILE;   // 1563
        gemm_kernel<<<blocks, 128>>>(h);
    }

    // 3) SpMM + bias + relu  (2 nodes per warp)
    {
        int nodes_per_block = 16;            // 8 warps x 2
        int blocks = (N_NODES + nodes_per_block - 1) / nodes_per_block;  // 6250
        spmm_kernel<<<blocks, 256>>>(edge_cols, edge_vals, b, out);
    }
}

// round 16
// speedup vs baseline: 1.1810x; 1.0484x over previous
#include <cuda_runtime.h>
#include <cuda_bf16.h>
#include <cuda_fp16.h>
#include <cstdint>

#define N_NODES 100000
#define D 128

// ---------------- scratch (device globals: no allocations allowed) ----------
__device__ int    g_rowptr[N_NODES + 1];
__device__ __half g_hW[(size_t)N_NODES * D];   // h @ W.T in fp16, 25.6 MB
// Pre-swizzled W fragments for mma.sync m16n8k16 fp16.
__device__ uint2 g_Whf[8 * 16 * 32];

// ---------------- Kernel 1: merged rowptr scatter (4x vec) + W prep ---------
__device__ __forceinline__ uint32_t pack2_h16(float x, float y) {
    __half2 v = __floats2half2_rn(x, y);
    return *(uint32_t*)&v;
}

__global__ void prep_kernel(const int* __restrict__ rows, int n_edges,
                            const float* __restrict__ W) {
    const int i = blockIdx.x * blockDim.x + threadIdx.x;

    // W fragment prep on the first 4096 threads.
    if (i < 8 * 16 * 32) {
        int t = i;
        int lane  = t & 31;
        int ntile = (t >> 5) & 15;
        int kstep = t >> 9;
        int n  = ntile * 8 + (lane >> 2);
        int k0 = kstep * 16 + (lane & 3) * 2;
        float w00 = __ldg(&W[n * 128 + k0]);
        float w01 = __ldg(&W[n * 128 + k0 + 1]);
        float w10 = __ldg(&W[n * 128 + k0 + 8]);
        float w11 = __ldg(&W[n * 128 + k0 + 9]);
        uint2 f;
        f.x = pack2_h16(w00, w01);
        f.y = pack2_h16(w10, w11);
        g_Whf[t] = f;
    }

    // rowptr scatter, 4 edges per thread.
    const int e0 = i * 4;
    if (e0 >= n_edges) return;

    int4 r;
    if (e0 + 3 < n_edges) {
        r = __ldg(&((const int4*)rows)[i]);
    } else {
        r.x = __ldg(&rows[e0]);
        r.y = (e0 + 1 < n_edges) ? __ldg(&rows[e0 + 1]) : r.x;
        r.z = (e0 + 2 < n_edges) ? __ldg(&rows[e0 + 2]) : r.y;
        r.w = (e0 + 3 < n_edges) ? __ldg(&rows[e0 + 3]) : r.z;
    }

    // Predecessor rows[e0-1]: neighbor lane's r.w; lane 0 loads it scalar.
    int prev = __shfl_up_sync(0xffffffffu, r.w, 1);
    if ((threadIdx.x & 31) == 0) {
        prev = (e0 == 0) ? -1 : __ldg(&rows[e0 - 1]);
    }

    const int rv[4] = {r.x, r.y, r.z, r.w};
    int a = prev;
    #pragma unroll
    for (int j = 0; j < 4; j++) {
        if (e0 + j < n_edges) {
            int b = rv[j];
            for (int k = a + 1; k <= b; k++) g_rowptr[k] = e0 + j;
            a = b;
        }
    }
    // Thread owning the last edge finishes the tail.
    if (e0 <= n_edges - 1 && e0 + 4 > n_edges - 1) {
        for (int k = a + 1; k <= N_NODES; k++) g_rowptr[k] = n_edges;
    }
}

// ---------------- Kernel 2: g = h @ W.T, smem-staged fp16 mma ----------------
// (unchanged — measured improvement)
#define MTILE 64
#define APAD  136

__device__ __forceinline__ void mma_f16(float* c, const uint32_t* a, uint2 b) {
    asm volatile(
        "mma.sync.aligned.m16n8k16.row.col.f32.f16.f16.f32 "
        "{%0,%1,%2,%3}, {%4,%5,%6,%7}, {%8,%9}, {%0,%1,%2,%3};"
        : "+f"(c[0]), "+f"(c[1]), "+f"(c[2]), "+f"(c[3])
        : "r"(a[0]), "r"(a[1]), "r"(a[2]), "r"(a[3]), "r"(b.x), "r"(b.y));
}

__global__ void __launch_bounds__(128, 4) gemm_kernel(
    const float* __restrict__ A)   // h [N_NODES, 128]
{
    __shared__ __half sA[MTILE * APAD];   // 17.4 KB

    const int tid    = threadIdx.x;
    const int lane   = tid & 31;
    const int warp   = tid >> 5;
    const int m_base = blockIdx.x * MTILE;

    #pragma unroll
    for (int q = 0; q < 16; q++) {
        int idx = q * 128 + tid;          // 0..2047
        int row = idx >> 5;
        int c4  = idx & 31;
        int rsrc = min(m_base + row, N_NODES - 1);
        float4 v = __ldg(&((const float4*)A)[(size_t)rsrc * 32 + c4]);
        __half2 p0 = __floats2half2_rn(v.x, v.y);
        __half2 p1 = __floats2half2_rn(v.z, v.w);
        *(__half2*)&sA[row * APAD + c4 * 4]     = p0;
        *(__half2*)&sA[row * APAD + c4 * 4 + 2] = p1;
    }
    __syncthreads();

    const int grp  = lane >> 2;
    const int quad = lane & 3;
    const int mrow = (warp >> 1) * 32;
    const int ntb  = (warp & 1) * 8;

    float acc[2][8][4];
    #pragma unroll
    for (int f = 0; f < 2; f++)
        #pragma unroll
        for (int nt = 0; nt < 8; nt++)
            #pragma unroll
            for (int i = 0; i < 4; i++) acc[f][nt][i] = 0.f;

    #pragma unroll
    for (int kstep = 0; kstep < 8; kstep++) {
        int kb = kstep * 16 + quad * 2;
        uint32_t a[2][4];
        #pragma unroll
        for (int f = 0; f < 2; f++) {
            int r = mrow + f * 16 + grp;
            a[f][0] = *(uint32_t*)&sA[r * APAD + kb];
            a[f][1] = *(uint32_t*)&sA[(r + 8) * APAD + kb];
            a[f][2] = *(uint32_t*)&sA[r * APAD + kb + 8];
            a[f][3] = *(uint32_t*)&sA[(r + 8) * APAD + kb + 8];
        }
        #pragma unroll
        for (int nt = 0; nt < 8; nt++) {
            uint2 wh = __ldg(&g_Whf[(kstep * 16 + ntb + nt) * 32 + lane]);
            mma_f16(acc[0][nt], a[0], wh);
            mma_f16(acc[1][nt], a[1], wh);
        }
    }
    __syncthreads();

    #pragma unroll
    for (int f = 0; f < 2; f++) {
        #pragma unroll
        for (int nt = 0; nt < 8; nt++) {
            int col = (ntb + nt) * 8 + quad * 2;
            int r0  = mrow + f * 16 + grp;
            *(__half2*)&sA[r0 * APAD + col] =
                __floats2half2_rn(acc[f][nt][0], acc[f][nt][1]);
            *(__half2*)&sA[(r0 + 8) * APAD + col] =
                __floats2half2_rn(acc[f][nt][2], acc[f][nt][3]);
        }
    }
    __syncthreads();

    #pragma unroll
    for (int q = 0; q < 8; q++) {
        int idx = q * 128 + tid;          // 0..1023
        int row = idx >> 4;
        int c16 = idx & 15;
        int rdst = m_base + row;
        if (rdst < N_NODES) {
            uint4 v = *(uint4*)&sA[row * APAD + c16 * 8];
            *(uint4*)&g_hW[(size_t)rdst * 128 + c16 * 8] = v;
        }
    }
}

// ---------------- Kernel 3: SpMM, half-warp per node, hfma2 flush-8 ---------
// (unchanged from R15 — measured improvement, rel_err 5.91e-4)
__global__ void __launch_bounds__(256) spmm_kernel(
    const int*   __restrict__ cols,
    const float* __restrict__ vals,
    const float* __restrict__ bias,
    float*       __restrict__ out)
{
    const int warp_id = (blockIdx.x * blockDim.x + threadIdx.x) >> 5;
    const unsigned lane = threadIdx.x & 31;
    const unsigned hl   = lane & 15;          // lane within half-warp
    const int nid = warp_id * 2 + (int)(lane >> 4);
    if (warp_id * 2 >= N_NODES) return;

    int start = 0, end = 0;
    if (nid < N_NODES) {
        start = g_rowptr[nid];
        end   = g_rowptr[nid + 1];
    }
    const int deg  = end - start;
    const int odeg = __shfl_xor_sync(0xffffffffu, deg, 16);
    const int ntrips = (max(deg, odeg) + 15) >> 4;   // warp-uniform

    const uint4* __restrict__ g4 = ((const uint4*)g_hW) + hl;   // row = 16 uint4

    float acc[8];
    #pragma unroll
    for (int i = 0; i < 8; i++) acc[i] = 0.f;

    for (int t = 0; t < ntrips; t++) {
        int e = start + t * 16 + (int)hl;
        int   c = 0; float v = 0.f;
        if (e < end) {
            c = __ldg(&cols[e]);
            v = __ldg(&vals[e]);
        }
        #pragma unroll
        for (int half = 0; half < 2; half++) {
            __half2 h0 = __float2half2_rn(0.f);
            __half2 h1 = __float2half2_rn(0.f);
            __half2 h2 = __float2half2_rn(0.f);
            __half2 h3 = __float2half2_rn(0.f);
            #pragma unroll
            for (int j = 0; j < 8; j++) {
                const int jj = half * 8 + j;
                unsigned cj = (unsigned)__shfl_sync(0xffffffffu, c, jj, 16);
                float    vj = __shfl_sync(0xffffffffu, v, jj, 16);
                __half2  vh = __float2half2_rn(vj);
                uint4 raw = __ldg(&g4[cj * 16u]);
                h0 = __hfma2(vh, *(__half2*)&raw.x, h0);
                h1 = __hfma2(vh, *(__half2*)&raw.y, h1);
                h2 = __hfma2(vh, *(__half2*)&raw.z, h2);
                h3 = __hfma2(vh, *(__half2*)&raw.w, h3);
            }
            // Flush to fp32.
            float2 f0 = __half22float2(h0);
            float2 f1 = __half22float2(h1);
            float2 f2 = __half22float2(h2);
            float2 f3 = __half22float2(h3);
            acc[0] += f0.x;  acc[1] += f0.y;
            acc[2] += f1.x;  acc[3] += f1.y;
            acc[4] += f2.x;  acc[5] += f2.y;
            acc[6] += f3.x;  acc[7] += f3.y;
        }
    }

    if (nid < N_NODES) {
        const float4* b4 = ((const float4*)bias) + hl * 2;
        float4 ba = __ldg(&b4[0]);
        float4 bb = __ldg(&b4[1]);
        float4 o0, o1;
        o0.x = fmaxf(acc[0] + ba.x, 0.f);
        o0.y = fmaxf(acc[1] + ba.y, 0.f);
        o0.z = fmaxf(acc[2] + ba.z, 0.f);
        o0.w = fmaxf(acc[3] + ba.w, 0.f);
        o1.x = fmaxf(acc[4] + bb.x, 0.f);
        o1.y = fmaxf(acc[5] + bb.y, 0.f);
        o1.z = fmaxf(acc[6] + bb.z, 0.f);
        o1.w = fmaxf(acc[7] + bb.w, 0.f);
        float4* orow = ((float4*)out) + (size_t)nid * 32 + hl * 2;
        orow[0] = o0;
        orow[1] = o1;
    }
}

// ---------------- launch ----------------------------------------------------
extern "C" void kernel_launch(void* const* d_in, const int* in_sizes, int n_in,
                              void* d_out, int out_size)
{
    const int*   edge_rows = (const int*)  d_in[0];
    const int*   edge_cols = (const int*)  d_in[1];
    const float* edge_vals = (const float*)d_in[2];
    const float* h         = (const float*)d_in[3];
    const float* W         = (const float*)d_in[4];
    const float* b         = (const float*)d_in[5];
    float*       out       = (float*)d_out;

    const int n_edges = in_sizes[0];

    // 1) merged rowptr scatter (4 edges/thread) + W fragment prep
    {
        int threads = 256;
        int nthreads_needed = (n_edges + 3) / 4;
        if (nthreads_needed < 8 * 16 * 32) nthreads_needed = 8 * 16 * 32;
        int blocks = (nthreads_needed + threads - 1) / threads;
        prep_kernel<<<blocks, threads>>>(edge_rows, n_edges, W);
    }

    // 2) g = h @ W.T  (smem-staged fp16 tensor cores, fp32 accumulate)
    {
        int blocks = (N_NODES + MTILE - 1) / MTILE;   // 1563
        gemm_kernel<<<blocks, 128>>>(h);
    }

    // 3) SpMM + bias + relu  (2 nodes per warp)
    {
        int nodes_per_block = 16;            // 8 warps x 2
        int blocks = (N_NODES + nodes_per_block - 1) / nodes_per_block;  // 6250
        spmm_kernel<<<blocks, 256>>>(edge_cols, edge_vals, b, out);
    }
}